// round 11
// baseline (speedup 1.0000x reference)
#include <cuda_runtime.h>
#include <cstdint>

#define BB 64
#define NN 1024

// Output layout (flattened reference tuple, all float32):
#define OFF_DONE 0
#define OFF_NM   1
#define OFF_ADJ  (1 + BB*NN)
#define OFF_FA   (OFF_ADJ + (size_t)BB*NN*NN)
#define OFF_PT   (OFF_FA + BB)
#define OFF_STEP (OFF_PT + BB)

#define BT 8
#define RR 16

// Single fused kernel: every block recomputes new_mask inline (no prep pass,
// no gmem round-trip), computes its i-tile's fpresent into smem, and streams
// its adj tile. Blocks with itile==0 also emit the new_mask rows; block 0's
// threads 128..191 handle done / present_time_new / fa / step.
__global__ __launch_bounds__(256) void k_fused(const float* __restrict__ inputs,
                                               const float* __restrict__ dist,
                                               const float* __restrict__ mask,
                                               const float* __restrict__ ptime,
                                               const int*   __restrict__ pres,
                                               const int*   __restrict__ fut,
                                               float* out)
{
    __shared__ float s_fp[BT][RR];     // fpresent[bb][r] for this block's tile
    __shared__ float s_nml[BB];        // block 0 only: new_mask[b, N-1]

    const int ITILES = NN / RR;        // 64
    int itile = blockIdx.x & (ITILES - 1);
    int b0    = (blockIdx.x >> 6) * BT;
    int i0    = itile * RR;
    int tid   = threadIdx.x;

    float T0 = inputs[3];              // inputs[0,0,ARR] — global scalar

    // ---- dlast for this thread's 4 columns (strided; L2-sector resident) ----
    float dl[4];
#pragma unroll
    for (int q = 0; q < 4; q++)
        dl[q] = __ldg(dist + (size_t)(tid + 256 * q) * NN + (NN - 1));

    // ---- fpresent for the i-tile: 128 threads, one (bb, r) each ----
    if (tid < BT * RR) {
        int bb = tid >> 4;             // RR = 16
        int r  = tid & 15;
        int b  = b0 + bb;
        int i  = i0 + r;
        int   pa = __ldg(pres + b);
        float pt = __ldg(ptime + b);
        float4 i4 = *reinterpret_cast<const float4*>(
            inputs + ((size_t)(b * NN + i)) * 4);
        float arrive = dist[(size_t)pa * NN + i] + pt;
        float w      = fmaxf(0.0f, i4.x - arrive);
        s_fp[bb][r]  = (arrive + w) + i4.z;
    }

    // ---- Block 0: small outputs (threads 128..191 -> one batch each) ----
    if (blockIdx.x == 0 && tid >= 128 && tid < 128 + BB) {
        int b = tid - 128;
        int   pa = __ldg(pres + b);
        float pt = __ldg(ptime + b);

        // new_mask[b, N-1] (exactly k_prep's formula)
        {
            int j = NN - 1;
            float4 i4 = *reinterpret_cast<const float4*>(
                inputs + ((size_t)(b * NN + j)) * 4);
            float dlastj = dist[(size_t)j * NN + (NN - 1)];
            float arrive = dist[(size_t)pa * NN + j] + pt;
            float w = fmaxf(0.0f, i4.x - arrive);
            float t = arrive + w;
            bool c1 = t <= i4.y;
            bool c2 = ((t + i4.z) + dlastj) <= T0;
            float m = mask[b * NN + j];
            if (j == pa) m = 0.0f;
            s_nml[b] = (c1 && c2) ? m : 0.0f;
        }

        // present_time_new[b] = fpresent-like at future_actions[b]
        int fb = __ldg(fut + b);
        float4 f4 = *reinterpret_cast<const float4*>(
            inputs + ((size_t)(b * NN + fb)) * 4);
        float arrj = dist[(size_t)pa * NN + fb] + pt;
        float wj   = fmaxf(0.0f, f4.x - arrj);
        out[OFF_PT + b]   = (arrj + wj) + f4.z;
        out[OFF_FA + b]   = (float)fb;
        out[OFF_STEP + b] = 1.0f;
    }

    __syncthreads();

    if (blockIdx.x == 0 && tid == 0) {
        float any = 0.0f;
#pragma unroll
        for (int b = 0; b < BB; b++) any = fmaxf(any, s_nml[b]);
        out[OFF_DONE] = (any > 0.0f) ? 0.0f : 1.0f;
    }

    // ---- Main: batch outer, rows inner (dist tile L1-resident across BT) ----
    for (int bb = 0; bb < BT; bb++) {
        int b = b0 + bb;
        int   pa = __ldg(pres + b);
        float pt = __ldg(ptime + b);
        const float* dpa = dist + (size_t)pa * NN;

        float op[4], cl[4], du[4], nm[4];
#pragma unroll
        for (int q = 0; q < 4; q++) {
            int j = tid + 256 * q;
            float4 i4 = *reinterpret_cast<const float4*>(
                inputs + ((size_t)(b * NN + j)) * 4);
            op[q] = i4.x; cl[q] = i4.y; du[q] = i4.z;

            // inline new_mask[b, j] — identical op order to k_prep
            float arrive = dpa[j] + pt;
            float w = fmaxf(0.0f, op[q] - arrive);
            float t = arrive + w;
            bool c1 = t <= cl[q];
            bool c2 = ((t + du[q]) + dl[q]) <= T0;
            float m = mask[b * NN + j];
            if (j == pa) m = 0.0f;
            nm[q] = (c1 && c2) ? m : 0.0f;
        }

        if (itile == 0) {              // emit new_mask rows once per batch
#pragma unroll
            for (int q = 0; q < 4; q++)
                out[OFF_NM + b * NN + tid + 256 * q] = nm[q];
        }

        float Tb = inputs[((size_t)b * NN) * 4 + 3];

#pragma unroll
        for (int r = 0; r < RR; r++) {
            int   i  = i0 + r;
            float fp = s_fp[bb][r];
            const float* drow = dist + (size_t)i * NN;
            float* orow = out + OFF_ADJ + ((size_t)(b * NN + i)) * NN;

#pragma unroll
            for (int q = 0; q < 4; q++) {
                int j = tid + 256 * q;
                float arr2 = drow[j] + fp;
                float w    = fmaxf(0.0f, op[q] - arr2);
                float s    = arr2 + w;
                bool a1 = s <= cl[q];
                bool a2 = ((s + du[q]) + dl[q]) <= Tb;
                float v = (a1 && a2) ? nm[q] : 0.0f;
                if (j == i) v = 1.0f;
                orow[j] = v;
            }
        }
    }
}

extern "C" void kernel_launch(void* const* d_in, const int* in_sizes, int n_in,
                              void* d_out, int out_size)
{
    const float* inputs = (const float*)d_in[0];   // (B, N, 4) f32
    const float* dist   = (const float*)d_in[1];   // (N, N)   f32
    const float* mask   = (const float*)d_in[2];   // (B, N)   f32
    const float* ptime  = (const float*)d_in[3];   // (B, 1)   f32
    const int*   pres   = (const int*)d_in[4];     // (B,)     i32
    const int*   fut    = (const int*)d_in[5];     // (B,)     i32
    float* out = (float*)d_out;

    k_fused<<<(NN / RR) * (BB / BT), 256>>>(inputs, dist, mask, ptime, pres, fut, out);
}

// round 12
// speedup vs baseline: 1.6457x; 1.6457x over previous
#include <cuda_runtime.h>
#include <cstdint>

#define BB 64
#define NN 1024

// Output layout (flattened reference tuple, all float32):
#define OFF_DONE 0
#define OFF_NM   1
#define OFF_ADJ  (1 + BB*NN)
#define OFF_FA   (OFF_ADJ + (size_t)BB*NN*NN)
#define OFF_PT   (OFF_FA + BB)
#define OFF_STEP (OFF_PT + BB)

__device__ float g_fp[BB * NN];     // fpresent[b, i]
__device__ float g_dlast[NN];       // dist[:, N-1] contiguous
__device__ float g_nmlast[BB];      // new_mask[b, N-1] (for `done` reduction)

__global__ void k_prep(const float* __restrict__ inputs,
                       const float* __restrict__ dist,
                       const float* __restrict__ mask,
                       const float* __restrict__ ptime,
                       const int*   __restrict__ pres,
                       const int*   __restrict__ fut,
                       float* out)
{
    int b = blockIdx.x;
    int j = threadIdx.x;

    int   pa = pres[b];
    float pt = ptime[b];

    float4 in4 = *reinterpret_cast<const float4*>(inputs + ((size_t)(b * NN + j)) * 4);
    float op = in4.x, cl = in4.y, dur = in4.z;
    float T0 = inputs[3];

    float dlast  = dist[(size_t)j * NN + (NN - 1)];
    float arrive = dist[(size_t)pa * NN + j] + pt;
    float wait   = fmaxf(0.0f, op - arrive);
    float t      = arrive + wait;

    bool c1 = t <= cl;
    bool c2 = ((t + dur) + dlast) <= T0;

    float m = mask[b * NN + j];
    if (j == pa) m = 0.0f;
    float nm = (c1 && c2) ? m : 0.0f;

    float fpres = t + dur;

    out[OFF_NM + b * NN + j] = nm;
    g_fp[b * NN + j] = fpres;
    if (b == 0) g_dlast[j] = dlast;
    if (j == NN - 1) g_nmlast[b] = nm;

    int fb = fut[b];
    if (j == fb) out[OFF_PT + b] = fpres;
    if (j == 0) {
        out[OFF_FA + b]   = (float)fb;
        out[OFF_STEP + b] = 1.0f;
    }
}

// adj kernel — the champion interior exactly as R1 (fully coalesced scalar,
// no smem, ptxas unconstrained -> ~124 regs, deep load batching), with the
// `done` reduction folded into block 0 (replaces the separate k_init launch).
#define BT 4
#define RR 8

__global__ __launch_bounds__(256) void k_adj(const float* __restrict__ inputs,
                                             const float* __restrict__ dist,
                                             float* out)
{
    const int ITILES = NN / RR;                 // 128
    int itile = blockIdx.x & (ITILES - 1);
    int b0    = (blockIdx.x / ITILES) * BT;
    int i0    = itile * RR;
    int tid   = threadIdx.x;

    if (blockIdx.x == 0 && tid == 0) {
        float any = 0.0f;
#pragma unroll
        for (int b = 0; b < BB; b++) any = fmaxf(any, g_nmlast[b]);
        out[OFF_DONE] = (any > 0.0f) ? 0.0f : 1.0f;
    }

    float dl[4];
#pragma unroll
    for (int q = 0; q < 4; q++) dl[q] = g_dlast[tid + 256 * q];

    const float* nm_base = out + OFF_NM;

    for (int bb = 0; bb < BT; bb++) {
        int b = b0 + bb;

        float op[4], cl[4], du[4], nm[4];
#pragma unroll
        for (int q = 0; q < 4; q++) {
            int j = tid + 256 * q;
            float4 in4 = *reinterpret_cast<const float4*>(
                inputs + ((size_t)(b * NN + j)) * 4);
            op[q] = in4.x; cl[q] = in4.y; du[q] = in4.z;
            nm[q] = nm_base[b * NN + j];
        }
        float Tb = inputs[((size_t)b * NN) * 4 + 3];

#pragma unroll
        for (int r = 0; r < RR; r++) {
            int   i  = i0 + r;
            float fp = g_fp[b * NN + i];
            const float* drow = dist + (size_t)i * NN;
            float* orow = out + OFF_ADJ + ((size_t)(b * NN + i)) * NN;

#pragma unroll
            for (int q = 0; q < 4; q++) {
                int j = tid + 256 * q;
                float arr2 = drow[j] + fp;
                float w    = fmaxf(0.0f, op[q] - arr2);
                float s    = arr2 + w;
                bool a1 = s <= cl[q];
                bool a2 = ((s + du[q]) + dl[q]) <= Tb;
                float v = (a1 && a2) ? nm[q] : 0.0f;
                if (j == i) v = 1.0f;
                orow[j] = v;
            }
        }
    }
}

extern "C" void kernel_launch(void* const* d_in, const int* in_sizes, int n_in,
                              void* d_out, int out_size)
{
    const float* inputs = (const float*)d_in[0];   // (B, N, 4) f32
    const float* dist   = (const float*)d_in[1];   // (N, N)   f32
    const float* mask   = (const float*)d_in[2];   // (B, N)   f32
    const float* ptime  = (const float*)d_in[3];   // (B, 1)   f32
    const int*   pres   = (const int*)d_in[4];     // (B,)     i32
    const int*   fut    = (const int*)d_in[5];     // (B,)     i32
    float* out = (float*)d_out;

    k_prep<<<BB, NN>>>(inputs, dist, mask, ptime, pres, fut, out);
    k_adj<<<(NN / RR) * (BB / BT), 256>>>(inputs, dist, out);
}

// round 13
// speedup vs baseline: 1.6975x; 1.0315x over previous
#include <cuda_runtime.h>
#include <cstdint>

#define BB 64
#define NN 1024

// Output layout (flattened reference tuple, all float32):
#define OFF_DONE 0
#define OFF_NM   1
#define OFF_ADJ  (1 + BB*NN)
#define OFF_FA   (OFF_ADJ + (size_t)BB*NN*NN)
#define OFF_PT   (OFF_FA + BB)
#define OFF_STEP (OFF_PT + BB)

__device__ float g_fp[BB * NN];     // fpresent[b, i]
__device__ float g_dlast[NN];       // dist[:, N-1]
__device__ float g_nmlast[BB];      // new_mask[b, N-1]
__device__ float g_op[BB * NN];     // SoA copies of inputs (for aligned loads)
__device__ float g_cl[BB * NN];
__device__ float g_du[BB * NN];

__global__ void k_prep(const float* __restrict__ inputs,
                       const float* __restrict__ dist,
                       const float* __restrict__ mask,
                       const float* __restrict__ ptime,
                       const int*   __restrict__ pres,
                       const int*   __restrict__ fut,
                       float* out)
{
    int b = blockIdx.x;
    int j = threadIdx.x;

    int   pa = pres[b];
    float pt = ptime[b];

    float4 in4 = *reinterpret_cast<const float4*>(inputs + ((size_t)(b * NN + j)) * 4);
    float op = in4.x, cl = in4.y, dur = in4.z;
    float T0 = inputs[3];

    float dlast  = dist[(size_t)j * NN + (NN - 1)];
    float arrive = dist[(size_t)pa * NN + j] + pt;
    float wait   = fmaxf(0.0f, op - arrive);
    float t      = arrive + wait;

    bool c1 = t <= cl;
    bool c2 = ((t + dur) + dlast) <= T0;

    float m = mask[b * NN + j];
    if (j == pa) m = 0.0f;
    float nm = (c1 && c2) ? m : 0.0f;

    float fpres = t + dur;

    out[OFF_NM + b * NN + j] = nm;
    g_fp[b * NN + j] = fpres;
    g_op[b * NN + j] = op;
    g_cl[b * NN + j] = cl;
    g_du[b * NN + j] = dur;
    if (b == 0) g_dlast[j] = dlast;
    if (j == NN - 1) g_nmlast[b] = nm;

    int fb = fut[b];
    if (j == fb) out[OFF_PT + b] = fpres;
    if (j == 0) {
        out[OFF_FA + b]   = (float)fb;
        out[OFF_STEP + b] = 1.0f;
    }
}

// Assemble x[jb..jb+3] (jb = j4+3) from own aligned float4 a = [j4..j4+3] and
// the next lane's values via shfl; lane 31 substitutes its extra load bx.
__device__ __forceinline__ void shift3(float4 a, float4 bx, bool haveB, float o[4])
{
    o[0] = a.w;
    o[1] = __shfl_down_sync(0xffffffffu, a.x, 1);
    o[2] = __shfl_down_sync(0xffffffffu, a.y, 1);
    o[3] = __shfl_down_sync(0xffffffffu, a.z, 1);
    if (haveB) { o[1] = bx.x; o[2] = bx.y; o[3] = bx.z; }
}

// adj kernel — aligned float4 stores at jb=128w+4l+3 (4 wf/128 elem, the
// byte minimum) fed by aligned non-overlapping float4 loads + 3 SHFLs.
// Inputs come from SoA scratch (g_op/g_cl/g_du) with the same trick; nm is
// naturally aligned at jb. Warp 7 lane 31 stores scalar j=1023; threads 0..2
// handle j in {0,1,2} in a tail loop. Tiling identical to the champion.
#define BT 4
#define RR 8

__global__ __launch_bounds__(256) void k_adj(const float* __restrict__ inputs,
                                             const float* __restrict__ dist,
                                             float* out)
{
    const int ITILES = NN / RR;                 // 128
    int itile = blockIdx.x & (ITILES - 1);
    int b0    = (blockIdx.x / ITILES) * BT;
    int i0    = itile * RR;
    int tid   = threadIdx.x;
    int warp  = tid >> 5;
    int lane  = tid & 31;
    int jw    = warp << 7;
    int j4    = jw + 4 * lane;                  // aligned load base
    int jb    = j4 + 3;                         // aligned store base

    bool tail  = (warp == 7 && lane == 31);     // stores only scalar j=1023
    bool haveB = (lane == 31) && (warp < 7);    // needs next-chunk float4

    if (blockIdx.x == 0 && tid == 0) {
        float any = 0.0f;
#pragma unroll
        for (int b = 0; b < BB; b++) any = fmaxf(any, g_nmlast[b]);
        out[OFF_DONE] = (any > 0.0f) ? 0.0f : 1.0f;
    }

    float dl[4];
#pragma unroll
    for (int e = 0; e < 4; e++) dl[e] = g_dlast[min(jb + e, NN - 1)];

    const float4 zf4 = make_float4(0.f, 0.f, 0.f, 0.f);

    for (int bb = 0; bb < BT; bb++) {
        int b = b0 + bb;
        const float* opb = g_op + b * NN;
        const float* clb = g_cl + b * NN;
        const float* dub = g_du + b * NN;

        float4 aop = *reinterpret_cast<const float4*>(opb + j4);
        float4 acl = *reinterpret_cast<const float4*>(clb + j4);
        float4 adu = *reinterpret_cast<const float4*>(dub + j4);
        float4 bop = zf4, bcl = zf4, bdu = zf4;
        if (haveB) {
            bop = *reinterpret_cast<const float4*>(opb + jw + 128);
            bcl = *reinterpret_cast<const float4*>(clb + jw + 128);
            bdu = *reinterpret_cast<const float4*>(dub + jw + 128);
        }
        float op[4], cl[4], du[4];
        shift3(aop, bop, haveB, op);
        shift3(acl, bcl, haveB, cl);
        shift3(adu, bdu, haveB, du);

        float4 nm4 = *reinterpret_cast<const float4*>(out + OFF_NM + b * NN + jb);
        float nm[4] = {nm4.x, nm4.y, nm4.z, nm4.w};

        float Tb = inputs[((size_t)b * NN) * 4 + 3];

#pragma unroll
        for (int r = 0; r < RR; r++) {
            int   i  = i0 + r;
            float fp = g_fp[b * NN + i];
            const float* drow = dist + (size_t)i * NN;
            float* orow = out + OFF_ADJ + ((size_t)(b * NN + i)) * NN;

            float4 ad = *reinterpret_cast<const float4*>(drow + j4);
            float4 bd = zf4;
            if (haveB) bd = *reinterpret_cast<const float4*>(drow + jw + 128);
            float d[4];
            shift3(ad, bd, haveB, d);

            float v[4];
#pragma unroll
            for (int e = 0; e < 4; e++) {
                float arr2 = d[e] + fp;
                float w    = fmaxf(0.0f, op[e] - arr2);
                float s    = arr2 + w;
                bool a1 = s <= cl[e];
                bool a2 = ((s + du[e]) + dl[e]) <= Tb;
                float x = (a1 && a2) ? nm[e] : 0.0f;
                if (jb + e == i) x = 1.0f;
                v[e] = x;
            }
            if (!tail)
                *reinterpret_cast<float4*>(orow + jb) =
                    make_float4(v[0], v[1], v[2], v[3]);
            else
                orow[NN - 1] = v[0];
        }
    }

    // Leftover columns j in {0, 1, 2}
    if (tid < 3) {
        int j = tid;
        float dlL = g_dlast[j];
        for (int bb = 0; bb < BT; bb++) {
            int b = b0 + bb;
            float opL = g_op[b * NN + j];
            float clL = g_cl[b * NN + j];
            float duL = g_du[b * NN + j];
            float nmL = out[OFF_NM + b * NN + j];
            float Tb  = inputs[((size_t)b * NN) * 4 + 3];
#pragma unroll
            for (int r = 0; r < RR; r++) {
                int i = i0 + r;
                float fp = g_fp[b * NN + i];
                float arr2 = dist[(size_t)i * NN + j] + fp;
                float w    = fmaxf(0.0f, opL - arr2);
                float s    = arr2 + w;
                bool a1 = s <= clL;
                bool a2 = ((s + duL) + dlL) <= Tb;
                float x = (a1 && a2) ? nmL : 0.0f;
                if (j == i) x = 1.0f;
                out[OFF_ADJ + ((size_t)(b * NN + i)) * NN + j] = x;
            }
        }
    }
}

extern "C" void kernel_launch(void* const* d_in, const int* in_sizes, int n_in,
                              void* d_out, int out_size)
{
    const float* inputs = (const float*)d_in[0];   // (B, N, 4) f32
    const float* dist   = (const float*)d_in[1];   // (N, N)   f32
    const float* mask   = (const float*)d_in[2];   // (B, N)   f32
    const float* ptime  = (const float*)d_in[3];   // (B, 1)   f32
    const int*   pres   = (const int*)d_in[4];     // (B,)     i32
    const int*   fut    = (const int*)d_in[5];     // (B,)     i32
    float* out = (float*)d_out;

    k_prep<<<BB, NN>>>(inputs, dist, mask, ptime, pres, fut, out);
    k_adj<<<(NN / RR) * (BB / BT), 256>>>(inputs, dist, out);
}